// round 14
// baseline (speedup 1.0000x reference)
#include <cuda_runtime.h>
#include <cuda_fp16.h>
#include <cstdint>

#define N_USERS    100000
#define N_ENTITIES 100000
#define N_NODES    200000
#define D          64
#define E_KG       1500000
#define E_PREF     1500000
#define NNZ        1000000

// ---------------- scratch (no device allocation allowed) ----------------
__device__ __half g_ent16_in[(size_t)N_ENTITIES * D];
__device__ __half g_usr16_in[(size_t)N_USERS * D];
__device__ __half g_ent_b16 [(size_t)N_ENTITIES * D];
__device__ __half g_ent_c16 [(size_t)N_ENTITIES * D];
__device__ __half g_usr_b16 [(size_t)N_USERS * D];     // pref0 r0, user half (also hop-1 source)
__device__ __half g_pr0e16 [(size_t)N_ENTITIES * D];   // pref0 r0, entity-node half
__device__ __half g_w16 [16 * D];   // kg weight fp16
__device__ __half g_ew16[32 * D];   // pref weight fp16
__device__ float  g_fent_a[N_ENTITIES];
__device__ float  g_fent_b[N_ENTITIES];

__device__ int g_cnt_kg[N_ENTITIES];
__device__ int g_cnt_pf[N_NODES];
__device__ int g_cnt_it[N_USERS];
__device__ int g_bs_kg[1024];
__device__ int g_bs_pf[1024];
__device__ int g_bs_it[1024];
__device__ int g_offs_kg[N_ENTITIES + 1];
__device__ int g_offs_pf[N_NODES + 1];
__device__ int g_offs_it[N_USERS + 1];
__device__ int g_cur_kg[N_ENTITIES];
__device__ int g_cur_pf[N_NODES];
__device__ int g_cur_it[N_USERS];
__device__ unsigned g_ekg[E_KG];    // tail | (type-1)<<18
__device__ unsigned g_epf[E_PREF];  // tail | type<<18
__device__ int2     g_eit[NNZ];     // (col, float_bits(val))

// ---------------- CSR build ----------------

__global__ void count_k(const int* __restrict__ head, int E, int* __restrict__ cnt) {
    int i = blockIdx.x * blockDim.x + threadIdx.x;
    if (i < E) atomicAdd(&cnt[head[i]], 1);
}

__global__ void scan_block_k(const int* __restrict__ cnt, int n,
                             int* __restrict__ offs, int* __restrict__ bsums) {
    __shared__ int sh[1024];
    int idx = blockIdx.x * 1024 + threadIdx.x;
    int v = (idx < n) ? cnt[idx] : 0;
    sh[threadIdx.x] = v;
    __syncthreads();
    #pragma unroll
    for (int off = 1; off < 1024; off <<= 1) {
        int t = (threadIdx.x >= off) ? sh[threadIdx.x - off] : 0;
        __syncthreads();
        sh[threadIdx.x] += t;
        __syncthreads();
    }
    if (idx < n) offs[idx] = sh[threadIdx.x] - v;
    if (threadIdx.x == 1023) bsums[blockIdx.x] = sh[1023];
}

// parallel exclusive scan of block sums (nb <= 256)
__global__ void scan_final_k(int* __restrict__ bsums, int nb, int* __restrict__ offs,
                             int n, int total) {
    __shared__ int sh[256];
    int v = ((int)threadIdx.x < nb) ? bsums[threadIdx.x] : 0;
    sh[threadIdx.x] = v;
    __syncthreads();
    #pragma unroll
    for (int off = 1; off < 256; off <<= 1) {
        int t = (threadIdx.x >= off) ? sh[threadIdx.x - off] : 0;
        __syncthreads();
        sh[threadIdx.x] += t;
        __syncthreads();
    }
    if ((int)threadIdx.x < nb) bsums[threadIdx.x] = sh[threadIdx.x] - v;
    if (threadIdx.x == 0) offs[n] = total;
}

__global__ void add_offs_k(int* __restrict__ offs, int* __restrict__ cursor,
                           const int* __restrict__ bsums, int n) {
    int idx = blockIdx.x * 1024 + threadIdx.x;
    if (idx < n) {
        int v = offs[idx] + bsums[blockIdx.x];
        offs[idx] = v;
        cursor[idx] = v;
    }
}

__global__ void fill_packed_k(const int* __restrict__ head, const int* __restrict__ tail,
                              const int* __restrict__ type, int E, int typeBias,
                              int* __restrict__ cursor, unsigned* __restrict__ out) {
    int e = blockIdx.x * blockDim.x + threadIdx.x;
    if (e >= E) return;
    int p = atomicAdd(&cursor[head[e]], 1);
    out[p] = (unsigned)tail[e] | ((unsigned)(type[e] - typeBias) << 18);
}

__global__ void fill_it_k(const int* __restrict__ rows, const int* __restrict__ cols,
                          const float* __restrict__ vals,
                          int* __restrict__ cursor, int2* __restrict__ out) {
    int e = blockIdx.x * blockDim.x + threadIdx.x;
    if (e >= NNZ) return;
    int p = atomicAdd(&cursor[rows[e]], 1);
    out[p] = make_int2(cols[e], __float_as_int(vals[e]));
}

// ---------------- fp32 -> fp16 conversion ----------------

__global__ void conv16_k(const float* __restrict__ src, __half* __restrict__ dst, int n4) {
    int i = blockIdx.x * blockDim.x + threadIdx.x;
    if (i >= n4) return;
    float4 v = __ldg((const float4*)src + i);
    __half2 a = __floats2half2_rn(v.x, v.y);
    __half2 b = __floats2half2_rn(v.z, v.w);
    uint2 u;
    u.x = *reinterpret_cast<unsigned*>(&a);
    u.y = *reinterpret_cast<unsigned*>(&b);
    ((uint2*)dst)[i] = u;
}

// ---------- gathers: 8 lanes / row, 8 halves (16B) / lane ----------

__device__ __forceinline__ void accum_hh(float* acc, uint4 x, uint4 w) {
    float2 x0 = __half22float2(*reinterpret_cast<__half2*>(&x.x));
    float2 x1 = __half22float2(*reinterpret_cast<__half2*>(&x.y));
    float2 x2 = __half22float2(*reinterpret_cast<__half2*>(&x.z));
    float2 x3 = __half22float2(*reinterpret_cast<__half2*>(&x.w));
    float2 w0 = __half22float2(*reinterpret_cast<__half2*>(&w.x));
    float2 w1 = __half22float2(*reinterpret_cast<__half2*>(&w.y));
    float2 w2 = __half22float2(*reinterpret_cast<__half2*>(&w.z));
    float2 w3 = __half22float2(*reinterpret_cast<__half2*>(&w.w));
    acc[0] += x0.x * w0.x; acc[1] += x0.y * w0.y;
    acc[2] += x1.x * w1.x; acc[3] += x1.y * w1.y;
    acc[4] += x2.x * w2.x; acc[5] += x2.y * w2.y;
    acc[6] += x3.x * w3.x; acc[7] += x3.y * w3.y;
}

__device__ __forceinline__ void accum_hs(float* acc, uint4 h, float v) {
    float2 f0 = __half22float2(*reinterpret_cast<__half2*>(&h.x));
    float2 f1 = __half22float2(*reinterpret_cast<__half2*>(&h.y));
    float2 f2 = __half22float2(*reinterpret_cast<__half2*>(&h.z));
    float2 f3 = __half22float2(*reinterpret_cast<__half2*>(&h.w));
    acc[0] += f0.x * v; acc[1] += f0.y * v;
    acc[2] += f1.x * v; acc[3] += f1.y * v;
    acc[4] += f2.x * v; acc[5] += f2.y * v;
    acc[6] += f3.x * v; acc[7] += f3.y * v;
}

__device__ __forceinline__ float group_sumsq8(const float* a) {
    float ss = 0.f;
    #pragma unroll
    for (int k = 0; k < 8; k++) ss += a[k] * a[k];
    ss += __shfl_xor_sync(0xffffffffu, ss, 1);
    ss += __shfl_xor_sync(0xffffffffu, ss, 2);
    ss += __shfl_xor_sync(0xffffffffu, ss, 4);
    return ss;
}

__device__ __forceinline__ uint4 pack8(const float* r, float sc) {
    __half2 a = __floats2half2_rn(r[0] * sc, r[1] * sc);
    __half2 b = __floats2half2_rn(r[2] * sc, r[3] * sc);
    __half2 c = __floats2half2_rn(r[4] * sc, r[5] * sc);
    __half2 d = __floats2half2_rn(r[6] * sc, r[7] * sc);
    uint4 u;
    u.x = *reinterpret_cast<unsigned*>(&a);
    u.y = *reinterpret_cast<unsigned*>(&b);
    u.z = *reinterpret_cast<unsigned*>(&c);
    u.w = *reinterpret_cast<unsigned*>(&d);
    return u;
}

__device__ __forceinline__ float2 h2f(unsigned u) {
    return __half22float2(*reinterpret_cast<__half2*>(&u));
}

// entity agg: acc = sum(ent16[tail] * w16[type]); out16 = l2norm (fp16);
// out32 (optional, final output) = l2norm fp32 via streaming store;
// f_out = ||acc||/max(deg,1)
__global__ void __launch_bounds__(256)
gather_kg_h(const __half* __restrict__ ent16, const __half* __restrict__ w16,
            const int* __restrict__ offs, const unsigned* __restrict__ edges,
            __half* __restrict__ out16, float* __restrict__ out32,
            float* __restrict__ f_out) {
    int t = blockIdx.x * blockDim.x + threadIdx.x;
    int w = t >> 3, ln = t & 7;
    if (w >= N_ENTITIES) return;
    int s = __ldg(&offs[w]), e = __ldg(&offs[w + 1]);
    float acc[8] = {0, 0, 0, 0, 0, 0, 0, 0};
    int i = s;
    for (; i + 3 < e; i += 4) {
        unsigned p0 = __ldg(&edges[i]);
        unsigned p1 = __ldg(&edges[i + 1]);
        unsigned p2 = __ldg(&edges[i + 2]);
        unsigned p3 = __ldg(&edges[i + 3]);
        uint4 h0 = __ldg((const uint4*)(ent16 + (size_t)(p0 & 0x3FFFF) * D) + ln);
        uint4 h1 = __ldg((const uint4*)(ent16 + (size_t)(p1 & 0x3FFFF) * D) + ln);
        uint4 h2 = __ldg((const uint4*)(ent16 + (size_t)(p2 & 0x3FFFF) * D) + ln);
        uint4 h3 = __ldg((const uint4*)(ent16 + (size_t)(p3 & 0x3FFFF) * D) + ln);
        uint4 w0 = __ldg((const uint4*)(w16 + (size_t)(p0 >> 18) * D) + ln);
        uint4 w1 = __ldg((const uint4*)(w16 + (size_t)(p1 >> 18) * D) + ln);
        uint4 w2 = __ldg((const uint4*)(w16 + (size_t)(p2 >> 18) * D) + ln);
        uint4 w3 = __ldg((const uint4*)(w16 + (size_t)(p3 >> 18) * D) + ln);
        accum_hh(acc, h0, w0); accum_hh(acc, h1, w1);
        accum_hh(acc, h2, w2); accum_hh(acc, h3, w3);
    }
    for (; i < e; i++) {
        unsigned p0 = __ldg(&edges[i]);
        uint4 h0 = __ldg((const uint4*)(ent16 + (size_t)(p0 & 0x3FFFF) * D) + ln);
        uint4 w0 = __ldg((const uint4*)(w16 + (size_t)(p0 >> 18) * D) + ln);
        accum_hh(acc, h0, w0);
    }
    float nrm = fmaxf(sqrtf(group_sumsq8(acc)), 1e-12f);
    float sc = 1.0f / nrm;
    ((uint4*)(out16 + (size_t)w * D))[ln] = pack8(acc, sc);
    if (out32) {
        float4* o = (float4*)(out32 + (size_t)w * D) + ln * 2;
        __stcs(o,     make_float4(acc[0] * sc, acc[1] * sc, acc[2] * sc, acc[3] * sc));
        __stcs(o + 1, make_float4(acc[4] * sc, acc[5] * sc, acc[6] * sc, acc[7] * sc));
    }
    if (ln == 0) f_out[w] = nrm / fmaxf((float)(e - s), 1.0f);
}

// node agg: r = l2norm(sum(all16[tail] * ew16[type]))
// mode 0: store r fp16 only — usr_next16 (w < N_USERS) / pr0e16 (w >= N_USERS).
//         out_node NOT touched.
// mode 1: out_node = init + toFloat(r0 fp16) + r   (single streaming store)
__global__ void __launch_bounds__(256)
gather_pref_h(const __half* __restrict__ usr16, const __half* __restrict__ ent16,
              const __half* __restrict__ ew16,
              const int* __restrict__ offs, const unsigned* __restrict__ edges,
              __half* __restrict__ usr_next16, __half* __restrict__ pr0e16,
              float* __restrict__ out_node,
              const float* __restrict__ user0, const float* __restrict__ ent0,
              int mode) {
    int t = blockIdx.x * blockDim.x + threadIdx.x;
    int w = t >> 3, ln = t & 7;
    if (w >= N_NODES) return;
    int s = __ldg(&offs[w]), e = __ldg(&offs[w + 1]);
    float acc[8] = {0, 0, 0, 0, 0, 0, 0, 0};
    int i = s;
    for (; i + 3 < e; i += 4) {
        unsigned p0 = __ldg(&edges[i]);
        unsigned p1 = __ldg(&edges[i + 1]);
        unsigned p2 = __ldg(&edges[i + 2]);
        unsigned p3 = __ldg(&edges[i + 3]);
        int t0 = p0 & 0x3FFFF, t1 = p1 & 0x3FFFF, t2 = p2 & 0x3FFFF, t3 = p3 & 0x3FFFF;
        const __half* s0 = (t0 < N_USERS) ? (usr16 + (size_t)t0 * D)
                                          : (ent16 + (size_t)(t0 - N_USERS) * D);
        const __half* s1 = (t1 < N_USERS) ? (usr16 + (size_t)t1 * D)
                                          : (ent16 + (size_t)(t1 - N_USERS) * D);
        const __half* s2 = (t2 < N_USERS) ? (usr16 + (size_t)t2 * D)
                                          : (ent16 + (size_t)(t2 - N_USERS) * D);
        const __half* s3 = (t3 < N_USERS) ? (usr16 + (size_t)t3 * D)
                                          : (ent16 + (size_t)(t3 - N_USERS) * D);
        uint4 h0 = __ldg((const uint4*)s0 + ln);
        uint4 h1 = __ldg((const uint4*)s1 + ln);
        uint4 h2 = __ldg((const uint4*)s2 + ln);
        uint4 h3 = __ldg((const uint4*)s3 + ln);
        uint4 w0 = __ldg((const uint4*)(ew16 + (size_t)(p0 >> 18) * D) + ln);
        uint4 w1 = __ldg((const uint4*)(ew16 + (size_t)(p1 >> 18) * D) + ln);
        uint4 w2 = __ldg((const uint4*)(ew16 + (size_t)(p2 >> 18) * D) + ln);
        uint4 w3 = __ldg((const uint4*)(ew16 + (size_t)(p3 >> 18) * D) + ln);
        accum_hh(acc, h0, w0); accum_hh(acc, h1, w1);
        accum_hh(acc, h2, w2); accum_hh(acc, h3, w3);
    }
    for (; i < e; i++) {
        unsigned p0 = __ldg(&edges[i]);
        int t0 = p0 & 0x3FFFF;
        const __half* s0 = (t0 < N_USERS) ? (usr16 + (size_t)t0 * D)
                                          : (ent16 + (size_t)(t0 - N_USERS) * D);
        uint4 h0 = __ldg((const uint4*)s0 + ln);
        uint4 w0 = __ldg((const uint4*)(ew16 + (size_t)(p0 >> 18) * D) + ln);
        accum_hh(acc, h0, w0);
    }
    float sc = 1.0f / fmaxf(sqrtf(group_sumsq8(acc)), 1e-12f);
    if (mode == 0) {
        // store r0 fp16 only; out_node untouched
        uint4 r16 = pack8(acc, sc);
        if (w < N_USERS)
            ((uint4*)(usr_next16 + (size_t)w * D))[ln] = r16;
        else
            ((uint4*)(pr0e16 + (size_t)(w - N_USERS) * D))[ln] = r16;
    } else {
        // final: out_node = init + r0(fp16) + r1
        const float* ip;
        const __half* r0p;
        if (w < N_USERS) {
            ip  = user0 + (size_t)w * D;
            r0p = usr_next16 + (size_t)w * D;   // usr_b16 passed here
        } else {
            ip  = ent0 + (size_t)(w - N_USERS) * D;
            r0p = pr0e16 + (size_t)(w - N_USERS) * D;
        }
        const float4* iv = (const float4*)ip + ln * 2;
        float4 i0 = __ldg(iv), i1 = __ldg(iv + 1);
        uint4 r0h = __ldg((const uint4*)r0p + ln);
        float2 a = h2f(r0h.x), b = h2f(r0h.y), c = h2f(r0h.z), d = h2f(r0h.w);
        float4* o = (float4*)(out_node + (size_t)w * D) + ln * 2;
        __stcs(o, make_float4(i0.x + a.x + acc[0] * sc, i0.y + a.y + acc[1] * sc,
                              i0.z + b.x + acc[2] * sc, i0.w + b.y + acc[3] * sc));
        __stcs(o + 1, make_float4(i1.x + c.x + acc[4] * sc, i1.y + c.y + acc[5] * sc,
                                  i1.z + d.x + acc[6] * sc, i1.w + d.y + acc[7] * sc));
    }
}

// user: r = l2norm(sum(val * f[col] * ent16[col]))
__global__ void __launch_bounds__(256)
gather_it_h(const __half* __restrict__ ent16, const float* __restrict__ f,
            const int* __restrict__ offs, const int2* __restrict__ edges,
            float* __restrict__ out_user, const float* __restrict__ user0, int mode) {
    int t = blockIdx.x * blockDim.x + threadIdx.x;
    int w = t >> 3, ln = t & 7;
    if (w >= N_USERS) return;
    int s = __ldg(&offs[w]), e = __ldg(&offs[w + 1]);
    float acc[8] = {0, 0, 0, 0, 0, 0, 0, 0};
    int i = s;
    for (; i + 3 < e; i += 4) {
        int2 e0 = __ldg(&edges[i]);
        int2 e1 = __ldg(&edges[i + 1]);
        int2 e2 = __ldg(&edges[i + 2]);
        int2 e3 = __ldg(&edges[i + 3]);
        float v0 = __int_as_float(e0.y) * __ldg(&f[e0.x]);
        float v1 = __int_as_float(e1.y) * __ldg(&f[e1.x]);
        float v2 = __int_as_float(e2.y) * __ldg(&f[e2.x]);
        float v3 = __int_as_float(e3.y) * __ldg(&f[e3.x]);
        uint4 h0 = __ldg((const uint4*)(ent16 + (size_t)e0.x * D) + ln);
        uint4 h1 = __ldg((const uint4*)(ent16 + (size_t)e1.x * D) + ln);
        uint4 h2 = __ldg((const uint4*)(ent16 + (size_t)e2.x * D) + ln);
        uint4 h3 = __ldg((const uint4*)(ent16 + (size_t)e3.x * D) + ln);
        accum_hs(acc, h0, v0); accum_hs(acc, h1, v1);
        accum_hs(acc, h2, v2); accum_hs(acc, h3, v3);
    }
    for (; i < e; i++) {
        int2 e0 = __ldg(&edges[i]);
        float v0 = __int_as_float(e0.y) * __ldg(&f[e0.x]);
        uint4 h0 = __ldg((const uint4*)(ent16 + (size_t)e0.x * D) + ln);
        accum_hs(acc, h0, v0);
    }
    float sc = 1.0f / fmaxf(sqrtf(group_sumsq8(acc)), 1e-12f);
    float4* o = (float4*)(out_user + (size_t)w * D) + ln * 2;
    if (mode == 0) {
        const float4* up = (const float4*)(user0 + (size_t)w * D) + ln * 2;
        float4 u0 = __ldg(up), u1 = __ldg(up + 1);
        __stcs(o, make_float4(u0.x + acc[0] * sc, u0.y + acc[1] * sc,
                              u0.z + acc[2] * sc, u0.w + acc[3] * sc));
        __stcs(o + 1, make_float4(u1.x + acc[4] * sc, u1.y + acc[5] * sc,
                                  u1.z + acc[6] * sc, u1.w + acc[7] * sc));
    } else {
        float4 a0 = __ldcs(o), a1 = __ldcs(o + 1);
        __stcs(o, make_float4(a0.x + acc[0] * sc, a0.y + acc[1] * sc,
                              a0.z + acc[2] * sc, a0.w + acc[3] * sc));
        __stcs(o + 1, make_float4(a1.x + acc[4] * sc, a1.y + acc[5] * sc,
                                  a1.z + acc[6] * sc, a1.w + acc[7] * sc));
    }
}

// ---------------- launch ----------------

static void build_csr(cudaStream_t st, const int* head, int E, int n,
                      int* offs, int* cursor, int* cnt, int* bsums) {
    cudaMemsetAsync(cnt, 0, n * sizeof(int), st);
    count_k<<<(E + 255) / 256, 256, 0, st>>>(head, E, cnt);
    int nb = (n + 1023) / 1024;
    scan_block_k<<<nb, 1024, 0, st>>>(cnt, n, offs, bsums);
    scan_final_k<<<1, 256, 0, st>>>(bsums, nb, offs, n, E);
    add_offs_k<<<nb, 1024, 0, st>>>(offs, cursor, bsums, n);
}

extern "C" void kernel_launch(void* const* d_in, const int* in_sizes, int n_in,
                              void* d_out, int out_size) {
    const float* user_emb         = (const float*)d_in[0];
    const float* entity_emb       = (const float*)d_in[1];
    const float* weight           = (const float*)d_in[2];
    const float* extra_weight     = (const float*)d_in[3];
    const float* interact_vals    = (const float*)d_in[4];
    const int*   edge_index       = (const int*)d_in[5];
    const int*   edge_type        = (const int*)d_in[6];
    const int*   extra_edge_index = (const int*)d_in[7];
    const int*   extra_edge_type  = (const int*)d_in[8];
    const int*   interact_idx     = (const int*)d_in[9];
    float* out = (float*)d_out;

    const int* kg_head = edge_index;
    const int* kg_tail = edge_index + E_KG;
    const int* pf_head = extra_edge_index;
    const int* pf_tail = extra_edge_index + E_PREF;
    const int* it_rows = interact_idx;
    const int* it_cols = interact_idx + NNZ;

    static cudaStream_t sA = nullptr, sB = nullptr;
    static cudaEvent_t evFork, evCE, evKG0, evIT0, evPref;
    if (!sA) {
        cudaStreamCreateWithFlags(&sA, cudaStreamNonBlocking);
        cudaStreamCreateWithFlags(&sB, cudaStreamNonBlocking);
        cudaEventCreateWithFlags(&evFork, cudaEventDisableTiming);
        cudaEventCreateWithFlags(&evCE,   cudaEventDisableTiming);
        cudaEventCreateWithFlags(&evKG0,  cudaEventDisableTiming);
        cudaEventCreateWithFlags(&evIT0,  cudaEventDisableTiming);
        cudaEventCreateWithFlags(&evPref, cudaEventDisableTiming);
    }

    __half *ent16_in, *usr16_in, *ent_b16, *ent_c16, *usr_b16, *pr0e16, *w16, *ew16;
    float *fent_a, *fent_b;
    int *cnt_kg, *cnt_pf, *cnt_it, *bs_kg, *bs_pf, *bs_it;
    int *offs_kg, *offs_pf, *offs_it, *cur_kg, *cur_pf, *cur_it;
    unsigned *ekg, *epf;
    int2 *eit;
    cudaGetSymbolAddress((void**)&ent16_in, g_ent16_in);
    cudaGetSymbolAddress((void**)&usr16_in, g_usr16_in);
    cudaGetSymbolAddress((void**)&ent_b16,  g_ent_b16);
    cudaGetSymbolAddress((void**)&ent_c16,  g_ent_c16);
    cudaGetSymbolAddress((void**)&usr_b16,  g_usr_b16);
    cudaGetSymbolAddress((void**)&pr0e16,   g_pr0e16);
    cudaGetSymbolAddress((void**)&w16,      g_w16);
    cudaGetSymbolAddress((void**)&ew16,     g_ew16);
    cudaGetSymbolAddress((void**)&fent_a,   g_fent_a);
    cudaGetSymbolAddress((void**)&fent_b,   g_fent_b);
    cudaGetSymbolAddress((void**)&cnt_kg,   g_cnt_kg);
    cudaGetSymbolAddress((void**)&cnt_pf,   g_cnt_pf);
    cudaGetSymbolAddress((void**)&cnt_it,   g_cnt_it);
    cudaGetSymbolAddress((void**)&bs_kg,    g_bs_kg);
    cudaGetSymbolAddress((void**)&bs_pf,    g_bs_pf);
    cudaGetSymbolAddress((void**)&bs_it,    g_bs_it);
    cudaGetSymbolAddress((void**)&offs_kg,  g_offs_kg);
    cudaGetSymbolAddress((void**)&offs_pf,  g_offs_pf);
    cudaGetSymbolAddress((void**)&offs_it,  g_offs_it);
    cudaGetSymbolAddress((void**)&cur_kg,   g_cur_kg);
    cudaGetSymbolAddress((void**)&cur_pf,   g_cur_pf);
    cudaGetSymbolAddress((void**)&cur_it,   g_cur_it);
    cudaGetSymbolAddress((void**)&ekg,      g_ekg);
    cudaGetSymbolAddress((void**)&epf,      g_epf);
    cudaGetSymbolAddress((void**)&eit,      g_eit);

    float* out_user = out;
    float* out_ent  = out + (size_t)N_USERS * D;
    float* out_node = out + (size_t)N_NODES * D;

    const int GB_ENT  = (N_ENTITIES * 8 + 255) / 256;
    const int GB_NODE = (N_NODES    * 8 + 255) / 256;
    const int GB_USER = (N_USERS    * 8 + 255) / 256;
    const int CV_ENT  = (N_ENTITIES * D / 4 + 255) / 256;
    const int CV_USR  = (N_USERS    * D / 4 + 255) / 256;

    // ---- fork ----
    cudaEventRecord(evFork, 0);
    cudaStreamWaitEvent(sA, evFork, 0);
    cudaStreamWaitEvent(sB, evFork, 0);

    // ---- stream B: fp16 conversions first (off main critical path), then interact CSR
    conv16_k<<<CV_ENT, 256, 0, sB>>>(entity_emb, ent16_in, N_ENTITIES * D / 4);
    conv16_k<<<1, 256, 0, sB>>>(weight, w16, 16 * D / 4);
    cudaEventRecord(evCE, sB);
    build_csr(sB, it_rows, NNZ, N_USERS, offs_it, cur_it, cnt_it, bs_it);
    fill_it_k<<<(NNZ + 255) / 256, 256, 0, sB>>>(it_rows, it_cols, interact_vals,
                                                 cur_it, eit);

    // ---- stream A: conversions + pref CSR + pref0 ----
    conv16_k<<<CV_USR, 256, 0, sA>>>(user_emb, usr16_in, N_USERS * D / 4);
    conv16_k<<<2, 256, 0, sA>>>(extra_weight, ew16, 32 * D / 4);
    build_csr(sA, pf_head, E_PREF, N_NODES, offs_pf, cur_pf, cnt_pf, bs_pf);
    fill_packed_k<<<(E_PREF + 255) / 256, 256, 0, sA>>>(pf_head, pf_tail, extra_edge_type,
                                                        E_PREF, 0, cur_pf, epf);
    cudaStreamWaitEvent(sA, evCE, 0);
    gather_pref_h<<<GB_NODE, 256, 0, sA>>>(usr16_in, ent16_in, ew16,
                                           offs_pf, epf, usr_b16, pr0e16, out_node,
                                           user_emb, entity_emb, 0);

    // ---- main: kg CSR starts immediately ----
    build_csr(0, kg_head, E_KG, N_ENTITIES, offs_kg, cur_kg, cnt_kg, bs_kg);
    fill_packed_k<<<(E_KG + 255) / 256, 256, 0, 0>>>(kg_head, kg_tail, edge_type,
                                                     E_KG, 1, cur_kg, ekg);

    // hop 0: entity agg
    cudaStreamWaitEvent(0, evCE, 0);
    gather_kg_h<<<GB_ENT, 256, 0, 0>>>(ent16_in, w16, offs_kg, ekg,
                                       ent_b16, nullptr, fent_a);
    cudaEventRecord(evKG0, 0);

    // hop 0 interact on stream B (parallel with kg1)
    cudaStreamWaitEvent(sB, evKG0, 0);
    gather_it_h<<<GB_USER, 256, 0, sB>>>(ent_b16, fent_a, offs_it, eit,
                                         out_user, user_emb, 0);
    cudaEventRecord(evIT0, sB);

    // hop 1 pref on stream A (composes out_node = init + r0 + r1)
    cudaStreamWaitEvent(sA, evKG0, 0);
    gather_pref_h<<<GB_NODE, 256, 0, sA>>>(usr_b16, ent_b16, ew16,
                                           offs_pf, epf, usr_b16, pr0e16, out_node,
                                           user_emb, entity_emb, 1);
    cudaEventRecord(evPref, sA);

    // hop 1: entity agg -> out_ent (fp32, streaming) + ent_c16
    gather_kg_h<<<GB_ENT, 256, 0, 0>>>(ent_b16, w16, offs_kg, ekg,
                                       ent_c16, out_ent, fent_b);

    // hop 1 interact
    cudaStreamWaitEvent(0, evIT0, 0);
    gather_it_h<<<GB_USER, 256, 0, 0>>>(ent_c16, fent_b, offs_it, eit,
                                        out_user, user_emb, 1);

    // ---- join ----
    cudaStreamWaitEvent(0, evPref, 0);
}

// round 15
// speedup vs baseline: 1.0309x; 1.0309x over previous
#include <cuda_runtime.h>
#include <cuda_fp16.h>
#include <cstdint>

#define N_USERS    100000
#define N_ENTITIES 100000
#define N_NODES    200000
#define D          64
#define E_KG       1500000
#define E_PREF     1500000
#define NNZ        1000000

// ---------------- scratch (no device allocation allowed) ----------------
__device__ __half g_ent16_in[(size_t)N_ENTITIES * D];
__device__ __half g_usr16_in[(size_t)N_USERS * D];
__device__ __half g_ent_b16 [(size_t)N_ENTITIES * D];
__device__ __half g_ent_c16 [(size_t)N_ENTITIES * D];
__device__ __half g_usr_b16 [(size_t)N_USERS * D];
__device__ __half g_w16 [16 * D];   // kg weight fp16
__device__ __half g_ew16[32 * D];   // pref weight fp16
__device__ float  g_fent_a[N_ENTITIES];
__device__ float  g_fent_b[N_ENTITIES];

__device__ int g_cnt_kg[N_ENTITIES];
__device__ int g_cnt_pf[N_NODES];
__device__ int g_cnt_it[N_USERS];
__device__ int g_bs_kg[1024];
__device__ int g_bs_pf[1024];
__device__ int g_bs_it[1024];
__device__ int g_offs_kg[N_ENTITIES + 1];
__device__ int g_offs_pf[N_NODES + 1];
__device__ int g_offs_it[N_USERS + 1];
__device__ int g_cur_kg[N_ENTITIES];
__device__ int g_cur_pf[N_NODES];
__device__ int g_cur_it[N_USERS];
__device__ unsigned g_ekg[E_KG];    // tail | (type-1)<<18
__device__ unsigned g_epf[E_PREF];  // tail | type<<18
__device__ int2     g_eit[NNZ];     // (col, float_bits(val))

// ---------------- CSR build (vectorized: 4 edges / thread) ----------------

__global__ void count4_k(const int* __restrict__ head, int E4, int* __restrict__ cnt) {
    int i = blockIdx.x * blockDim.x + threadIdx.x;
    if (i >= E4) return;
    int4 h = __ldg((const int4*)head + i);
    atomicAdd(&cnt[h.x], 1);
    atomicAdd(&cnt[h.y], 1);
    atomicAdd(&cnt[h.z], 1);
    atomicAdd(&cnt[h.w], 1);
}

__global__ void scan_block_k(const int* __restrict__ cnt, int n,
                             int* __restrict__ offs, int* __restrict__ bsums) {
    __shared__ int sh[1024];
    int idx = blockIdx.x * 1024 + threadIdx.x;
    int v = (idx < n) ? cnt[idx] : 0;
    sh[threadIdx.x] = v;
    __syncthreads();
    #pragma unroll
    for (int off = 1; off < 1024; off <<= 1) {
        int t = (threadIdx.x >= off) ? sh[threadIdx.x - off] : 0;
        __syncthreads();
        sh[threadIdx.x] += t;
        __syncthreads();
    }
    if (idx < n) offs[idx] = sh[threadIdx.x] - v;
    if (threadIdx.x == 1023) bsums[blockIdx.x] = sh[1023];
}

// parallel exclusive scan of block sums (nb <= 256)
__global__ void scan_final_k(int* __restrict__ bsums, int nb, int* __restrict__ offs,
                             int n, int total) {
    __shared__ int sh[256];
    int v = ((int)threadIdx.x < nb) ? bsums[threadIdx.x] : 0;
    sh[threadIdx.x] = v;
    __syncthreads();
    #pragma unroll
    for (int off = 1; off < 256; off <<= 1) {
        int t = (threadIdx.x >= off) ? sh[threadIdx.x - off] : 0;
        __syncthreads();
        sh[threadIdx.x] += t;
        __syncthreads();
    }
    if ((int)threadIdx.x < nb) bsums[threadIdx.x] = sh[threadIdx.x] - v;
    if (threadIdx.x == 0) offs[n] = total;
}

__global__ void add_offs_k(int* __restrict__ offs, int* __restrict__ cursor,
                           const int* __restrict__ bsums, int n) {
    int idx = blockIdx.x * 1024 + threadIdx.x;
    if (idx < n) {
        int v = offs[idx] + bsums[blockIdx.x];
        offs[idx] = v;
        cursor[idx] = v;
    }
}

__global__ void fill_packed4_k(const int* __restrict__ head, const int* __restrict__ tail,
                               const int* __restrict__ type, int E4, int typeBias,
                               int* __restrict__ cursor, unsigned* __restrict__ out) {
    int i = blockIdx.x * blockDim.x + threadIdx.x;
    if (i >= E4) return;
    int4 h = __ldg((const int4*)head + i);
    int4 ta = __ldg((const int4*)tail + i);
    int4 ty = __ldg((const int4*)type + i);
    int p0 = atomicAdd(&cursor[h.x], 1);
    int p1 = atomicAdd(&cursor[h.y], 1);
    int p2 = atomicAdd(&cursor[h.z], 1);
    int p3 = atomicAdd(&cursor[h.w], 1);
    out[p0] = (unsigned)ta.x | ((unsigned)(ty.x - typeBias) << 18);
    out[p1] = (unsigned)ta.y | ((unsigned)(ty.y - typeBias) << 18);
    out[p2] = (unsigned)ta.z | ((unsigned)(ty.z - typeBias) << 18);
    out[p3] = (unsigned)ta.w | ((unsigned)(ty.w - typeBias) << 18);
}

__global__ void fill_it4_k(const int* __restrict__ rows, const int* __restrict__ cols,
                           const float* __restrict__ vals, int E4,
                           int* __restrict__ cursor, int2* __restrict__ out) {
    int i = blockIdx.x * blockDim.x + threadIdx.x;
    if (i >= E4) return;
    int4 r = __ldg((const int4*)rows + i);
    int4 c = __ldg((const int4*)cols + i);
    float4 v = __ldg((const float4*)vals + i);
    int p0 = atomicAdd(&cursor[r.x], 1);
    int p1 = atomicAdd(&cursor[r.y], 1);
    int p2 = atomicAdd(&cursor[r.z], 1);
    int p3 = atomicAdd(&cursor[r.w], 1);
    out[p0] = make_int2(c.x, __float_as_int(v.x));
    out[p1] = make_int2(c.y, __float_as_int(v.y));
    out[p2] = make_int2(c.z, __float_as_int(v.z));
    out[p3] = make_int2(c.w, __float_as_int(v.w));
}

// ---------------- fp32 -> fp16 conversion ----------------

__global__ void conv16_k(const float* __restrict__ src, __half* __restrict__ dst, int n4) {
    int i = blockIdx.x * blockDim.x + threadIdx.x;
    if (i >= n4) return;
    float4 v = __ldg((const float4*)src + i);
    __half2 a = __floats2half2_rn(v.x, v.y);
    __half2 b = __floats2half2_rn(v.z, v.w);
    uint2 u;
    u.x = *reinterpret_cast<unsigned*>(&a);
    u.y = *reinterpret_cast<unsigned*>(&b);
    ((uint2*)dst)[i] = u;
}

// ---------- gathers: 8 lanes / row, 8 halves (16B) / lane (round-13 bodies) ----------

__device__ __forceinline__ void accum_hh(float* acc, uint4 x, uint4 w) {
    float2 x0 = __half22float2(*reinterpret_cast<__half2*>(&x.x));
    float2 x1 = __half22float2(*reinterpret_cast<__half2*>(&x.y));
    float2 x2 = __half22float2(*reinterpret_cast<__half2*>(&x.z));
    float2 x3 = __half22float2(*reinterpret_cast<__half2*>(&x.w));
    float2 w0 = __half22float2(*reinterpret_cast<__half2*>(&w.x));
    float2 w1 = __half22float2(*reinterpret_cast<__half2*>(&w.y));
    float2 w2 = __half22float2(*reinterpret_cast<__half2*>(&w.z));
    float2 w3 = __half22float2(*reinterpret_cast<__half2*>(&w.w));
    acc[0] += x0.x * w0.x; acc[1] += x0.y * w0.y;
    acc[2] += x1.x * w1.x; acc[3] += x1.y * w1.y;
    acc[4] += x2.x * w2.x; acc[5] += x2.y * w2.y;
    acc[6] += x3.x * w3.x; acc[7] += x3.y * w3.y;
}

__device__ __forceinline__ void accum_hs(float* acc, uint4 h, float v) {
    float2 f0 = __half22float2(*reinterpret_cast<__half2*>(&h.x));
    float2 f1 = __half22float2(*reinterpret_cast<__half2*>(&h.y));
    float2 f2 = __half22float2(*reinterpret_cast<__half2*>(&h.z));
    float2 f3 = __half22float2(*reinterpret_cast<__half2*>(&h.w));
    acc[0] += f0.x * v; acc[1] += f0.y * v;
    acc[2] += f1.x * v; acc[3] += f1.y * v;
    acc[4] += f2.x * v; acc[5] += f2.y * v;
    acc[6] += f3.x * v; acc[7] += f3.y * v;
}

__device__ __forceinline__ float group_sumsq8(const float* a) {
    float ss = 0.f;
    #pragma unroll
    for (int k = 0; k < 8; k++) ss += a[k] * a[k];
    ss += __shfl_xor_sync(0xffffffffu, ss, 1);
    ss += __shfl_xor_sync(0xffffffffu, ss, 2);
    ss += __shfl_xor_sync(0xffffffffu, ss, 4);
    return ss;
}

__device__ __forceinline__ uint4 pack8(const float* r, float sc) {
    __half2 a = __floats2half2_rn(r[0] * sc, r[1] * sc);
    __half2 b = __floats2half2_rn(r[2] * sc, r[3] * sc);
    __half2 c = __floats2half2_rn(r[4] * sc, r[5] * sc);
    __half2 d = __floats2half2_rn(r[6] * sc, r[7] * sc);
    uint4 u;
    u.x = *reinterpret_cast<unsigned*>(&a);
    u.y = *reinterpret_cast<unsigned*>(&b);
    u.z = *reinterpret_cast<unsigned*>(&c);
    u.w = *reinterpret_cast<unsigned*>(&d);
    return u;
}

// entity agg: acc = sum(ent16[tail] * w16[type]); out16 = l2norm (fp16);
// out32 (optional, final output) = l2norm fp32 via streaming store;
// f_out = ||acc||/max(deg,1)
__global__ void __launch_bounds__(256)
gather_kg_h(const __half* __restrict__ ent16, const __half* __restrict__ w16,
            const int* __restrict__ offs, const unsigned* __restrict__ edges,
            __half* __restrict__ out16, float* __restrict__ out32,
            float* __restrict__ f_out) {
    int t = blockIdx.x * blockDim.x + threadIdx.x;
    int w = t >> 3, ln = t & 7;
    if (w >= N_ENTITIES) return;
    int s = __ldg(&offs[w]), e = __ldg(&offs[w + 1]);
    float acc[8] = {0, 0, 0, 0, 0, 0, 0, 0};
    int i = s;
    for (; i + 3 < e; i += 4) {
        unsigned p0 = __ldg(&edges[i]);
        unsigned p1 = __ldg(&edges[i + 1]);
        unsigned p2 = __ldg(&edges[i + 2]);
        unsigned p3 = __ldg(&edges[i + 3]);
        uint4 h0 = __ldg((const uint4*)(ent16 + (size_t)(p0 & 0x3FFFF) * D) + ln);
        uint4 h1 = __ldg((const uint4*)(ent16 + (size_t)(p1 & 0x3FFFF) * D) + ln);
        uint4 h2 = __ldg((const uint4*)(ent16 + (size_t)(p2 & 0x3FFFF) * D) + ln);
        uint4 h3 = __ldg((const uint4*)(ent16 + (size_t)(p3 & 0x3FFFF) * D) + ln);
        uint4 w0 = __ldg((const uint4*)(w16 + (size_t)(p0 >> 18) * D) + ln);
        uint4 w1 = __ldg((const uint4*)(w16 + (size_t)(p1 >> 18) * D) + ln);
        uint4 w2 = __ldg((const uint4*)(w16 + (size_t)(p2 >> 18) * D) + ln);
        uint4 w3 = __ldg((const uint4*)(w16 + (size_t)(p3 >> 18) * D) + ln);
        accum_hh(acc, h0, w0); accum_hh(acc, h1, w1);
        accum_hh(acc, h2, w2); accum_hh(acc, h3, w3);
    }
    for (; i < e; i++) {
        unsigned p0 = __ldg(&edges[i]);
        uint4 h0 = __ldg((const uint4*)(ent16 + (size_t)(p0 & 0x3FFFF) * D) + ln);
        uint4 w0 = __ldg((const uint4*)(w16 + (size_t)(p0 >> 18) * D) + ln);
        accum_hh(acc, h0, w0);
    }
    float nrm = fmaxf(sqrtf(group_sumsq8(acc)), 1e-12f);
    float sc = 1.0f / nrm;
    ((uint4*)(out16 + (size_t)w * D))[ln] = pack8(acc, sc);
    if (out32) {
        float4* o = (float4*)(out32 + (size_t)w * D) + ln * 2;
        __stcs(o,     make_float4(acc[0] * sc, acc[1] * sc, acc[2] * sc, acc[3] * sc));
        __stcs(o + 1, make_float4(acc[4] * sc, acc[5] * sc, acc[6] * sc, acc[7] * sc));
    }
    if (ln == 0) f_out[w] = nrm / fmaxf((float)(e - s), 1.0f);
}

// node agg: r = l2norm(sum(all16[tail] * ew16[type]))
__global__ void __launch_bounds__(256)
gather_pref_h(const __half* __restrict__ usr16, const __half* __restrict__ ent16,
              const __half* __restrict__ ew16,
              const int* __restrict__ offs, const unsigned* __restrict__ edges,
              __half* __restrict__ usr_next16, float* __restrict__ out_node,
              const float* __restrict__ user0, const float* __restrict__ ent0,
              int mode) {
    int t = blockIdx.x * blockDim.x + threadIdx.x;
    int w = t >> 3, ln = t & 7;
    if (w >= N_NODES) return;
    int s = __ldg(&offs[w]), e = __ldg(&offs[w + 1]);
    float acc[8] = {0, 0, 0, 0, 0, 0, 0, 0};
    int i = s;
    for (; i + 3 < e; i += 4) {
        unsigned p0 = __ldg(&edges[i]);
        unsigned p1 = __ldg(&edges[i + 1]);
        unsigned p2 = __ldg(&edges[i + 2]);
        unsigned p3 = __ldg(&edges[i + 3]);
        int t0 = p0 & 0x3FFFF, t1 = p1 & 0x3FFFF, t2 = p2 & 0x3FFFF, t3 = p3 & 0x3FFFF;
        const __half* s0 = (t0 < N_USERS) ? (usr16 + (size_t)t0 * D)
                                          : (ent16 + (size_t)(t0 - N_USERS) * D);
        const __half* s1 = (t1 < N_USERS) ? (usr16 + (size_t)t1 * D)
                                          : (ent16 + (size_t)(t1 - N_USERS) * D);
        const __half* s2 = (t2 < N_USERS) ? (usr16 + (size_t)t2 * D)
                                          : (ent16 + (size_t)(t2 - N_USERS) * D);
        const __half* s3 = (t3 < N_USERS) ? (usr16 + (size_t)t3 * D)
                                          : (ent16 + (size_t)(t3 - N_USERS) * D);
        uint4 h0 = __ldg((const uint4*)s0 + ln);
        uint4 h1 = __ldg((const uint4*)s1 + ln);
        uint4 h2 = __ldg((const uint4*)s2 + ln);
        uint4 h3 = __ldg((const uint4*)s3 + ln);
        uint4 w0 = __ldg((const uint4*)(ew16 + (size_t)(p0 >> 18) * D) + ln);
        uint4 w1 = __ldg((const uint4*)(ew16 + (size_t)(p1 >> 18) * D) + ln);
        uint4 w2 = __ldg((const uint4*)(ew16 + (size_t)(p2 >> 18) * D) + ln);
        uint4 w3 = __ldg((const uint4*)(ew16 + (size_t)(p3 >> 18) * D) + ln);
        accum_hh(acc, h0, w0); accum_hh(acc, h1, w1);
        accum_hh(acc, h2, w2); accum_hh(acc, h3, w3);
    }
    for (; i < e; i++) {
        unsigned p0 = __ldg(&edges[i]);
        int t0 = p0 & 0x3FFFF;
        const __half* s0 = (t0 < N_USERS) ? (usr16 + (size_t)t0 * D)
                                          : (ent16 + (size_t)(t0 - N_USERS) * D);
        uint4 h0 = __ldg((const uint4*)s0 + ln);
        uint4 w0 = __ldg((const uint4*)(ew16 + (size_t)(p0 >> 18) * D) + ln);
        accum_hh(acc, h0, w0);
    }
    float sc = 1.0f / fmaxf(sqrtf(group_sumsq8(acc)), 1e-12f);
    float4 r0 = make_float4(acc[0] * sc, acc[1] * sc, acc[2] * sc, acc[3] * sc);
    float4 r1 = make_float4(acc[4] * sc, acc[5] * sc, acc[6] * sc, acc[7] * sc);
    float4* o = (float4*)(out_node + (size_t)w * D) + ln * 2;
    if (mode == 0) {
        if (w < N_USERS)
            ((uint4*)(usr_next16 + (size_t)w * D))[ln] = pack8(acc, sc);
        __stcs(o, r0);
        __stcs(o + 1, r1);
    } else {
        const float* ip = (w < N_USERS) ? (user0 + (size_t)w * D)
                                        : (ent0 + (size_t)(w - N_USERS) * D);
        const float4* iv = (const float4*)ip + ln * 2;
        float4 i0 = __ldg(iv), i1 = __ldg(iv + 1);
        float4 a0 = __ldcs(o), a1 = __ldcs(o + 1);
        __stcs(o, make_float4(a0.x + i0.x + r0.x, a0.y + i0.y + r0.y,
                              a0.z + i0.z + r0.z, a0.w + i0.w + r0.w));
        __stcs(o + 1, make_float4(a1.x + i1.x + r1.x, a1.y + i1.y + r1.y,
                                  a1.z + i1.z + r1.z, a1.w + i1.w + r1.w));
    }
}

// user: r = l2norm(sum(val * f[col] * ent16[col]))
__global__ void __launch_bounds__(256)
gather_it_h(const __half* __restrict__ ent16, const float* __restrict__ f,
            const int* __restrict__ offs, const int2* __restrict__ edges,
            float* __restrict__ out_user, const float* __restrict__ user0, int mode) {
    int t = blockIdx.x * blockDim.x + threadIdx.x;
    int w = t >> 3, ln = t & 7;
    if (w >= N_USERS) return;
    int s = __ldg(&offs[w]), e = __ldg(&offs[w + 1]);
    float acc[8] = {0, 0, 0, 0, 0, 0, 0, 0};
    int i = s;
    for (; i + 3 < e; i += 4) {
        int2 e0 = __ldg(&edges[i]);
        int2 e1 = __ldg(&edges[i + 1]);
        int2 e2 = __ldg(&edges[i + 2]);
        int2 e3 = __ldg(&edges[i + 3]);
        float v0 = __int_as_float(e0.y) * __ldg(&f[e0.x]);
        float v1 = __int_as_float(e1.y) * __ldg(&f[e1.x]);
        float v2 = __int_as_float(e2.y) * __ldg(&f[e2.x]);
        float v3 = __int_as_float(e3.y) * __ldg(&f[e3.x]);
        uint4 h0 = __ldg((const uint4*)(ent16 + (size_t)e0.x * D) + ln);
        uint4 h1 = __ldg((const uint4*)(ent16 + (size_t)e1.x * D) + ln);
        uint4 h2 = __ldg((const uint4*)(ent16 + (size_t)e2.x * D) + ln);
        uint4 h3 = __ldg((const uint4*)(ent16 + (size_t)e3.x * D) + ln);
        accum_hs(acc, h0, v0); accum_hs(acc, h1, v1);
        accum_hs(acc, h2, v2); accum_hs(acc, h3, v3);
    }
    for (; i < e; i++) {
        int2 e0 = __ldg(&edges[i]);
        float v0 = __int_as_float(e0.y) * __ldg(&f[e0.x]);
        uint4 h0 = __ldg((const uint4*)(ent16 + (size_t)e0.x * D) + ln);
        accum_hs(acc, h0, v0);
    }
    float sc = 1.0f / fmaxf(sqrtf(group_sumsq8(acc)), 1e-12f);
    float4* o = (float4*)(out_user + (size_t)w * D) + ln * 2;
    if (mode == 0) {
        const float4* up = (const float4*)(user0 + (size_t)w * D) + ln * 2;
        float4 u0 = __ldg(up), u1 = __ldg(up + 1);
        __stcs(o, make_float4(u0.x + acc[0] * sc, u0.y + acc[1] * sc,
                              u0.z + acc[2] * sc, u0.w + acc[3] * sc));
        __stcs(o + 1, make_float4(u1.x + acc[4] * sc, u1.y + acc[5] * sc,
                                  u1.z + acc[6] * sc, u1.w + acc[7] * sc));
    } else {
        float4 a0 = __ldcs(o), a1 = __ldcs(o + 1);
        __stcs(o, make_float4(a0.x + acc[0] * sc, a0.y + acc[1] * sc,
                              a0.z + acc[2] * sc, a0.w + acc[3] * sc));
        __stcs(o + 1, make_float4(a1.x + acc[4] * sc, a1.y + acc[5] * sc,
                                  a1.z + acc[6] * sc, a1.w + acc[7] * sc));
    }
}

// ---------------- launch ----------------

static void build_csr(cudaStream_t st, const int* head, int E, int n,
                      int* offs, int* cursor, int* cnt, int* bsums) {
    cudaMemsetAsync(cnt, 0, n * sizeof(int), st);
    count4_k<<<(E / 4 + 255) / 256, 256, 0, st>>>(head, E / 4, cnt);
    int nb = (n + 1023) / 1024;
    scan_block_k<<<nb, 1024, 0, st>>>(cnt, n, offs, bsums);
    scan_final_k<<<1, 256, 0, st>>>(bsums, nb, offs, n, E);
    add_offs_k<<<nb, 1024, 0, st>>>(offs, cursor, bsums, n);
}

extern "C" void kernel_launch(void* const* d_in, const int* in_sizes, int n_in,
                              void* d_out, int out_size) {
    const float* user_emb         = (const float*)d_in[0];
    const float* entity_emb       = (const float*)d_in[1];
    const float* weight           = (const float*)d_in[2];
    const float* extra_weight     = (const float*)d_in[3];
    const float* interact_vals    = (const float*)d_in[4];
    const int*   edge_index       = (const int*)d_in[5];
    const int*   edge_type        = (const int*)d_in[6];
    const int*   extra_edge_index = (const int*)d_in[7];
    const int*   extra_edge_type  = (const int*)d_in[8];
    const int*   interact_idx     = (const int*)d_in[9];
    float* out = (float*)d_out;

    const int* kg_head = edge_index;
    const int* kg_tail = edge_index + E_KG;
    const int* pf_head = extra_edge_index;
    const int* pf_tail = extra_edge_index + E_PREF;
    const int* it_rows = interact_idx;
    const int* it_cols = interact_idx + NNZ;

    static cudaStream_t sA = nullptr, sB = nullptr;
    static cudaEvent_t evFork, evCE, evKG0, evIT0, evPref;
    if (!sA) {
        cudaStreamCreateWithFlags(&sA, cudaStreamNonBlocking);
        cudaStreamCreateWithFlags(&sB, cudaStreamNonBlocking);
        cudaEventCreateWithFlags(&evFork, cudaEventDisableTiming);
        cudaEventCreateWithFlags(&evCE,   cudaEventDisableTiming);
        cudaEventCreateWithFlags(&evKG0,  cudaEventDisableTiming);
        cudaEventCreateWithFlags(&evIT0,  cudaEventDisableTiming);
        cudaEventCreateWithFlags(&evPref, cudaEventDisableTiming);
    }

    __half *ent16_in, *usr16_in, *ent_b16, *ent_c16, *usr_b16, *w16, *ew16;
    float *fent_a, *fent_b;
    int *cnt_kg, *cnt_pf, *cnt_it, *bs_kg, *bs_pf, *bs_it;
    int *offs_kg, *offs_pf, *offs_it, *cur_kg, *cur_pf, *cur_it;
    unsigned *ekg, *epf;
    int2 *eit;
    cudaGetSymbolAddress((void**)&ent16_in, g_ent16_in);
    cudaGetSymbolAddress((void**)&usr16_in, g_usr16_in);
    cudaGetSymbolAddress((void**)&ent_b16,  g_ent_b16);
    cudaGetSymbolAddress((void**)&ent_c16,  g_ent_c16);
    cudaGetSymbolAddress((void**)&usr_b16,  g_usr_b16);
    cudaGetSymbolAddress((void**)&w16,      g_w16);
    cudaGetSymbolAddress((void**)&ew16,     g_ew16);
    cudaGetSymbolAddress((void**)&fent_a,   g_fent_a);
    cudaGetSymbolAddress((void**)&fent_b,   g_fent_b);
    cudaGetSymbolAddress((void**)&cnt_kg,   g_cnt_kg);
    cudaGetSymbolAddress((void**)&cnt_pf,   g_cnt_pf);
    cudaGetSymbolAddress((void**)&cnt_it,   g_cnt_it);
    cudaGetSymbolAddress((void**)&bs_kg,    g_bs_kg);
    cudaGetSymbolAddress((void**)&bs_pf,    g_bs_pf);
    cudaGetSymbolAddress((void**)&bs_it,    g_bs_it);
    cudaGetSymbolAddress((void**)&offs_kg,  g_offs_kg);
    cudaGetSymbolAddress((void**)&offs_pf,  g_offs_pf);
    cudaGetSymbolAddress((void**)&offs_it,  g_offs_it);
    cudaGetSymbolAddress((void**)&cur_kg,   g_cur_kg);
    cudaGetSymbolAddress((void**)&cur_pf,   g_cur_pf);
    cudaGetSymbolAddress((void**)&cur_it,   g_cur_it);
    cudaGetSymbolAddress((void**)&ekg,      g_ekg);
    cudaGetSymbolAddress((void**)&epf,      g_epf);
    cudaGetSymbolAddress((void**)&eit,      g_eit);

    float* out_user = out;
    float* out_ent  = out + (size_t)N_USERS * D;
    float* out_node = out + (size_t)N_NODES * D;

    const int GB_ENT  = (N_ENTITIES * 8 + 255) / 256;
    const int GB_NODE = (N_NODES    * 8 + 255) / 256;
    const int GB_USER = (N_USERS    * 8 + 255) / 256;
    const int CV_ENT  = (N_ENTITIES * D / 4 + 255) / 256;
    const int CV_USR  = (N_USERS    * D / 4 + 255) / 256;

    // ---- fork ----
    cudaEventRecord(evFork, 0);
    cudaStreamWaitEvent(sA, evFork, 0);
    cudaStreamWaitEvent(sB, evFork, 0);

    // ---- stream B: fp16 conversions first (off main critical path), then interact CSR
    conv16_k<<<CV_ENT, 256, 0, sB>>>(entity_emb, ent16_in, N_ENTITIES * D / 4);
    conv16_k<<<1, 256, 0, sB>>>(weight, w16, 16 * D / 4);
    cudaEventRecord(evCE, sB);
    build_csr(sB, it_rows, NNZ, N_USERS, offs_it, cur_it, cnt_it, bs_it);
    fill_it4_k<<<(NNZ / 4 + 255) / 256, 256, 0, sB>>>(it_rows, it_cols, interact_vals,
                                                      NNZ / 4, cur_it, eit);

    // ---- stream A: conversions + pref CSR + pref0 ----
    conv16_k<<<CV_USR, 256, 0, sA>>>(user_emb, usr16_in, N_USERS * D / 4);
    conv16_k<<<2, 256, 0, sA>>>(extra_weight, ew16, 32 * D / 4);
    build_csr(sA, pf_head, E_PREF, N_NODES, offs_pf, cur_pf, cnt_pf, bs_pf);
    fill_packed4_k<<<(E_PREF / 4 + 255) / 256, 256, 0, sA>>>(pf_head, pf_tail,
                                                             extra_edge_type, E_PREF / 4,
                                                             0, cur_pf, epf);
    cudaStreamWaitEvent(sA, evCE, 0);
    gather_pref_h<<<GB_NODE, 256, 0, sA>>>(usr16_in, ent16_in, ew16,
                                           offs_pf, epf, usr_b16, out_node,
                                           user_emb, entity_emb, 0);

    // ---- main: kg CSR starts immediately ----
    build_csr(0, kg_head, E_KG, N_ENTITIES, offs_kg, cur_kg, cnt_kg, bs_kg);
    fill_packed4_k<<<(E_KG / 4 + 255) / 256, 256, 0, 0>>>(kg_head, kg_tail, edge_type,
                                                          E_KG / 4, 1, cur_kg, ekg);

    // hop 0: entity agg
    cudaStreamWaitEvent(0, evCE, 0);
    gather_kg_h<<<GB_ENT, 256, 0, 0>>>(ent16_in, w16, offs_kg, ekg,
                                       ent_b16, nullptr, fent_a);
    cudaEventRecord(evKG0, 0);

    // hop 0 interact on stream B (parallel with kg1)
    cudaStreamWaitEvent(sB, evKG0, 0);
    gather_it_h<<<GB_USER, 256, 0, sB>>>(ent_b16, fent_a, offs_it, eit,
                                         out_user, user_emb, 0);
    cudaEventRecord(evIT0, sB);

    // hop 1 pref on stream A
    cudaStreamWaitEvent(sA, evKG0, 0);
    gather_pref_h<<<GB_NODE, 256, 0, sA>>>(usr_b16, ent_b16, ew16,
                                           offs_pf, epf, nullptr, out_node,
                                           user_emb, entity_emb, 1);
    cudaEventRecord(evPref, sA);

    // hop 1: entity agg -> out_ent (fp32, streaming) + ent_c16
    gather_kg_h<<<GB_ENT, 256, 0, 0>>>(ent_b16, w16, offs_kg, ekg,
                                       ent_c16, out_ent, fent_b);

    // hop 1 interact
    cudaStreamWaitEvent(0, evIT0, 0);
    gather_it_h<<<GB_USER, 256, 0, 0>>>(ent_c16, fent_b, offs_it, eit,
                                        out_user, user_emb, 1);

    // ---- join ----
    cudaStreamWaitEvent(0, evPref, 0);
}

// round 16
// speedup vs baseline: 1.0386x; 1.0075x over previous
#include <cuda_runtime.h>
#include <cuda_fp16.h>
#include <cstdint>

#define N_USERS    100000
#define N_ENTITIES 100000
#define N_NODES    200000
#define D          64
#define E_KG       1500000
#define E_PREF     1500000
#define NNZ        1000000

// ---------------- scratch (no device allocation allowed) ----------------
__device__ __half g_ent16_in[(size_t)N_ENTITIES * D];
__device__ __half g_usr16_in[(size_t)N_USERS * D];
__device__ __half g_ent_b16 [(size_t)N_ENTITIES * D];
__device__ __half g_ent_c16 [(size_t)N_ENTITIES * D];
__device__ __half g_usr_b16 [(size_t)N_USERS * D];
__device__ __half g_w16 [16 * D];   // kg weight fp16
__device__ __half g_ew16[32 * D];   // pref weight fp16
__device__ float  g_fent_a[N_ENTITIES];
__device__ float  g_fent_b[N_ENTITIES];

__device__ int g_cnt_kg[N_ENTITIES];
__device__ int g_cnt_pf[N_NODES];
__device__ int g_cnt_it[N_USERS];
__device__ int g_bs_kg[1024];
__device__ int g_bs_pf[1024];
__device__ int g_bs_it[1024];
__device__ int g_offs_kg[N_ENTITIES + 4];
__device__ int g_offs_pf[N_NODES + 4];
__device__ int g_offs_it[N_USERS + 4];
__device__ int g_cur_kg[N_ENTITIES];
__device__ int g_cur_pf[N_NODES];
__device__ int g_cur_it[N_USERS];
__device__ unsigned g_ekg[E_KG];    // tail | (type-1)<<18
__device__ unsigned g_epf[E_PREF];  // tail | type<<18
__device__ int2     g_eit[NNZ];     // (col, float_bits(val))

// ---------------- CSR build (vectorized: 4 edges / thread) ----------------

__global__ void count4_k(const int* __restrict__ head, int E4, int* __restrict__ cnt) {
    int i = blockIdx.x * blockDim.x + threadIdx.x;
    if (i >= E4) return;
    int4 h = __ldg((const int4*)head + i);
    atomicAdd(&cnt[h.x], 1);
    atomicAdd(&cnt[h.y], 1);
    atomicAdd(&cnt[h.z], 1);
    atomicAdd(&cnt[h.w], 1);
}

// 1024 elems / block, 256 threads x int4; warp-shuffle scan, 2 barriers.
// n must be divisible by 4 (all our n are).
__global__ void scan_block4_k(const int* __restrict__ cnt, int n,
                              int* __restrict__ offs, int* __restrict__ bsums) {
    __shared__ int warpsum[8];
    int base = blockIdx.x * 1024;
    int idx  = base + (int)threadIdx.x * 4;
    int i4   = idx >> 2;
    int4 v = make_int4(0, 0, 0, 0);
    if (idx < n) v = __ldg((const int4*)cnt + i4);
    int s0 = v.x;
    int s1 = s0 + v.y;
    int s2 = s1 + v.z;
    int s3 = s2 + v.w;
    int lane = threadIdx.x & 31, wid = threadIdx.x >> 5;
    int ws = s3;
    #pragma unroll
    for (int off = 1; off < 32; off <<= 1) {
        int t = __shfl_up_sync(0xffffffffu, ws, off);
        if (lane >= off) ws += t;
    }
    if (lane == 31) warpsum[wid] = ws;
    __syncthreads();
    if (wid == 0 && lane < 8) {
        int x = warpsum[lane];
        #pragma unroll
        for (int off = 1; off < 8; off <<= 1) {
            int t = __shfl_up_sync(0xffu, x, off);
            if (lane >= off) x += t;
        }
        warpsum[lane] = x;
    }
    __syncthreads();
    int warppre = (wid > 0) ? warpsum[wid - 1] : 0;
    int thrpre  = warppre + ws - s3;   // exclusive prefix before this thread's 4 elems
    if (idx < n)
        ((int4*)offs)[i4] = make_int4(thrpre, thrpre + s0, thrpre + s1, thrpre + s2);
    if (threadIdx.x == 255) bsums[blockIdx.x] = warpsum[7];
}

// parallel exclusive scan of block sums (nb <= 256)
__global__ void scan_final_k(int* __restrict__ bsums, int nb, int* __restrict__ offs,
                             int n, int total) {
    __shared__ int sh[256];
    int v = ((int)threadIdx.x < nb) ? bsums[threadIdx.x] : 0;
    sh[threadIdx.x] = v;
    __syncthreads();
    #pragma unroll
    for (int off = 1; off < 256; off <<= 1) {
        int t = (threadIdx.x >= off) ? sh[threadIdx.x - off] : 0;
        __syncthreads();
        sh[threadIdx.x] += t;
        __syncthreads();
    }
    if ((int)threadIdx.x < nb) bsums[threadIdx.x] = sh[threadIdx.x] - v;
    if (threadIdx.x == 0) offs[n] = total;
}

// add block prefix, 4 elems/thread; writes offs + cursor.
__global__ void add_offs4_k(int* __restrict__ offs, int* __restrict__ cursor,
                            const int* __restrict__ bsums, int n4) {
    int i = blockIdx.x * blockDim.x + threadIdx.x;
    if (i >= n4) return;
    int b = __ldg(&bsums[(i * 4) >> 10]);
    int4 v = ((const int4*)offs)[i];
    v.x += b; v.y += b; v.z += b; v.w += b;
    ((int4*)offs)[i]   = v;
    ((int4*)cursor)[i] = v;
}

__global__ void fill_packed4_k(const int* __restrict__ head, const int* __restrict__ tail,
                               const int* __restrict__ type, int E4, int typeBias,
                               int* __restrict__ cursor, unsigned* __restrict__ out) {
    int i = blockIdx.x * blockDim.x + threadIdx.x;
    if (i >= E4) return;
    int4 h = __ldg((const int4*)head + i);
    int4 ta = __ldg((const int4*)tail + i);
    int4 ty = __ldg((const int4*)type + i);
    int p0 = atomicAdd(&cursor[h.x], 1);
    int p1 = atomicAdd(&cursor[h.y], 1);
    int p2 = atomicAdd(&cursor[h.z], 1);
    int p3 = atomicAdd(&cursor[h.w], 1);
    out[p0] = (unsigned)ta.x | ((unsigned)(ty.x - typeBias) << 18);
    out[p1] = (unsigned)ta.y | ((unsigned)(ty.y - typeBias) << 18);
    out[p2] = (unsigned)ta.z | ((unsigned)(ty.z - typeBias) << 18);
    out[p3] = (unsigned)ta.w | ((unsigned)(ty.w - typeBias) << 18);
}

__global__ void fill_it4_k(const int* __restrict__ rows, const int* __restrict__ cols,
                           const float* __restrict__ vals, int E4,
                           int* __restrict__ cursor, int2* __restrict__ out) {
    int i = blockIdx.x * blockDim.x + threadIdx.x;
    if (i >= E4) return;
    int4 r = __ldg((const int4*)rows + i);
    int4 c = __ldg((const int4*)cols + i);
    float4 v = __ldg((const float4*)vals + i);
    int p0 = atomicAdd(&cursor[r.x], 1);
    int p1 = atomicAdd(&cursor[r.y], 1);
    int p2 = atomicAdd(&cursor[r.z], 1);
    int p3 = atomicAdd(&cursor[r.w], 1);
    out[p0] = make_int2(c.x, __float_as_int(v.x));
    out[p1] = make_int2(c.y, __float_as_int(v.y));
    out[p2] = make_int2(c.z, __float_as_int(v.z));
    out[p3] = make_int2(c.w, __float_as_int(v.w));
}

// ---------------- fp32 -> fp16 conversion ----------------

__global__ void conv16_k(const float* __restrict__ src, __half* __restrict__ dst, int n4) {
    int i = blockIdx.x * blockDim.x + threadIdx.x;
    if (i >= n4) return;
    float4 v = __ldg((const float4*)src + i);
    __half2 a = __floats2half2_rn(v.x, v.y);
    __half2 b = __floats2half2_rn(v.z, v.w);
    uint2 u;
    u.x = *reinterpret_cast<unsigned*>(&a);
    u.y = *reinterpret_cast<unsigned*>(&b);
    ((uint2*)dst)[i] = u;
}

// ---------- gathers: 8 lanes / row, 8 halves (16B) / lane (round-13 bodies) ----------

__device__ __forceinline__ void accum_hh(float* acc, uint4 x, uint4 w) {
    float2 x0 = __half22float2(*reinterpret_cast<__half2*>(&x.x));
    float2 x1 = __half22float2(*reinterpret_cast<__half2*>(&x.y));
    float2 x2 = __half22float2(*reinterpret_cast<__half2*>(&x.z));
    float2 x3 = __half22float2(*reinterpret_cast<__half2*>(&x.w));
    float2 w0 = __half22float2(*reinterpret_cast<__half2*>(&w.x));
    float2 w1 = __half22float2(*reinterpret_cast<__half2*>(&w.y));
    float2 w2 = __half22float2(*reinterpret_cast<__half2*>(&w.z));
    float2 w3 = __half22float2(*reinterpret_cast<__half2*>(&w.w));
    acc[0] += x0.x * w0.x; acc[1] += x0.y * w0.y;
    acc[2] += x1.x * w1.x; acc[3] += x1.y * w1.y;
    acc[4] += x2.x * w2.x; acc[5] += x2.y * w2.y;
    acc[6] += x3.x * w3.x; acc[7] += x3.y * w3.y;
}

__device__ __forceinline__ void accum_hs(float* acc, uint4 h, float v) {
    float2 f0 = __half22float2(*reinterpret_cast<__half2*>(&h.x));
    float2 f1 = __half22float2(*reinterpret_cast<__half2*>(&h.y));
    float2 f2 = __half22float2(*reinterpret_cast<__half2*>(&h.z));
    float2 f3 = __half22float2(*reinterpret_cast<__half2*>(&h.w));
    acc[0] += f0.x * v; acc[1] += f0.y * v;
    acc[2] += f1.x * v; acc[3] += f1.y * v;
    acc[4] += f2.x * v; acc[5] += f2.y * v;
    acc[6] += f3.x * v; acc[7] += f3.y * v;
}

__device__ __forceinline__ float group_sumsq8(const float* a) {
    float ss = 0.f;
    #pragma unroll
    for (int k = 0; k < 8; k++) ss += a[k] * a[k];
    ss += __shfl_xor_sync(0xffffffffu, ss, 1);
    ss += __shfl_xor_sync(0xffffffffu, ss, 2);
    ss += __shfl_xor_sync(0xffffffffu, ss, 4);
    return ss;
}

__device__ __forceinline__ uint4 pack8(const float* r, float sc) {
    __half2 a = __floats2half2_rn(r[0] * sc, r[1] * sc);
    __half2 b = __floats2half2_rn(r[2] * sc, r[3] * sc);
    __half2 c = __floats2half2_rn(r[4] * sc, r[5] * sc);
    __half2 d = __floats2half2_rn(r[6] * sc, r[7] * sc);
    uint4 u;
    u.x = *reinterpret_cast<unsigned*>(&a);
    u.y = *reinterpret_cast<unsigned*>(&b);
    u.z = *reinterpret_cast<unsigned*>(&c);
    u.w = *reinterpret_cast<unsigned*>(&d);
    return u;
}

// entity agg: acc = sum(ent16[tail] * w16[type]); out16 = l2norm (fp16);
// out32 (optional, final output) = l2norm fp32 via streaming store;
// f_out = ||acc||/max(deg,1)
__global__ void __launch_bounds__(256)
gather_kg_h(const __half* __restrict__ ent16, const __half* __restrict__ w16,
            const int* __restrict__ offs, const unsigned* __restrict__ edges,
            __half* __restrict__ out16, float* __restrict__ out32,
            float* __restrict__ f_out) {
    int t = blockIdx.x * blockDim.x + threadIdx.x;
    int w = t >> 3, ln = t & 7;
    if (w >= N_ENTITIES) return;
    int s = __ldg(&offs[w]), e = __ldg(&offs[w + 1]);
    float acc[8] = {0, 0, 0, 0, 0, 0, 0, 0};
    int i = s;
    for (; i + 3 < e; i += 4) {
        unsigned p0 = __ldg(&edges[i]);
        unsigned p1 = __ldg(&edges[i + 1]);
        unsigned p2 = __ldg(&edges[i + 2]);
        unsigned p3 = __ldg(&edges[i + 3]);
        uint4 h0 = __ldg((const uint4*)(ent16 + (size_t)(p0 & 0x3FFFF) * D) + ln);
        uint4 h1 = __ldg((const uint4*)(ent16 + (size_t)(p1 & 0x3FFFF) * D) + ln);
        uint4 h2 = __ldg((const uint4*)(ent16 + (size_t)(p2 & 0x3FFFF) * D) + ln);
        uint4 h3 = __ldg((const uint4*)(ent16 + (size_t)(p3 & 0x3FFFF) * D) + ln);
        uint4 w0 = __ldg((const uint4*)(w16 + (size_t)(p0 >> 18) * D) + ln);
        uint4 w1 = __ldg((const uint4*)(w16 + (size_t)(p1 >> 18) * D) + ln);
        uint4 w2 = __ldg((const uint4*)(w16 + (size_t)(p2 >> 18) * D) + ln);
        uint4 w3 = __ldg((const uint4*)(w16 + (size_t)(p3 >> 18) * D) + ln);
        accum_hh(acc, h0, w0); accum_hh(acc, h1, w1);
        accum_hh(acc, h2, w2); accum_hh(acc, h3, w3);
    }
    for (; i < e; i++) {
        unsigned p0 = __ldg(&edges[i]);
        uint4 h0 = __ldg((const uint4*)(ent16 + (size_t)(p0 & 0x3FFFF) * D) + ln);
        uint4 w0 = __ldg((const uint4*)(w16 + (size_t)(p0 >> 18) * D) + ln);
        accum_hh(acc, h0, w0);
    }
    float nrm = fmaxf(sqrtf(group_sumsq8(acc)), 1e-12f);
    float sc = 1.0f / nrm;
    ((uint4*)(out16 + (size_t)w * D))[ln] = pack8(acc, sc);
    if (out32) {
        float4* o = (float4*)(out32 + (size_t)w * D) + ln * 2;
        __stcs(o,     make_float4(acc[0] * sc, acc[1] * sc, acc[2] * sc, acc[3] * sc));
        __stcs(o + 1, make_float4(acc[4] * sc, acc[5] * sc, acc[6] * sc, acc[7] * sc));
    }
    if (ln == 0) f_out[w] = nrm / fmaxf((float)(e - s), 1.0f);
}

// node agg: r = l2norm(sum(all16[tail] * ew16[type]))
__global__ void __launch_bounds__(256)
gather_pref_h(const __half* __restrict__ usr16, const __half* __restrict__ ent16,
              const __half* __restrict__ ew16,
              const int* __restrict__ offs, const unsigned* __restrict__ edges,
              __half* __restrict__ usr_next16, float* __restrict__ out_node,
              const float* __restrict__ user0, const float* __restrict__ ent0,
              int mode) {
    int t = blockIdx.x * blockDim.x + threadIdx.x;
    int w = t >> 3, ln = t & 7;
    if (w >= N_NODES) return;
    int s = __ldg(&offs[w]), e = __ldg(&offs[w + 1]);
    float acc[8] = {0, 0, 0, 0, 0, 0, 0, 0};
    int i = s;
    for (; i + 3 < e; i += 4) {
        unsigned p0 = __ldg(&edges[i]);
        unsigned p1 = __ldg(&edges[i + 1]);
        unsigned p2 = __ldg(&edges[i + 2]);
        unsigned p3 = __ldg(&edges[i + 3]);
        int t0 = p0 & 0x3FFFF, t1 = p1 & 0x3FFFF, t2 = p2 & 0x3FFFF, t3 = p3 & 0x3FFFF;
        const __half* s0 = (t0 < N_USERS) ? (usr16 + (size_t)t0 * D)
                                          : (ent16 + (size_t)(t0 - N_USERS) * D);
        const __half* s1 = (t1 < N_USERS) ? (usr16 + (size_t)t1 * D)
                                          : (ent16 + (size_t)(t1 - N_USERS) * D);
        const __half* s2 = (t2 < N_USERS) ? (usr16 + (size_t)t2 * D)
                                          : (ent16 + (size_t)(t2 - N_USERS) * D);
        const __half* s3 = (t3 < N_USERS) ? (usr16 + (size_t)t3 * D)
                                          : (ent16 + (size_t)(t3 - N_USERS) * D);
        uint4 h0 = __ldg((const uint4*)s0 + ln);
        uint4 h1 = __ldg((const uint4*)s1 + ln);
        uint4 h2 = __ldg((const uint4*)s2 + ln);
        uint4 h3 = __ldg((const uint4*)s3 + ln);
        uint4 w0 = __ldg((const uint4*)(ew16 + (size_t)(p0 >> 18) * D) + ln);
        uint4 w1 = __ldg((const uint4*)(ew16 + (size_t)(p1 >> 18) * D) + ln);
        uint4 w2 = __ldg((const uint4*)(ew16 + (size_t)(p2 >> 18) * D) + ln);
        uint4 w3 = __ldg((const uint4*)(ew16 + (size_t)(p3 >> 18) * D) + ln);
        accum_hh(acc, h0, w0); accum_hh(acc, h1, w1);
        accum_hh(acc, h2, w2); accum_hh(acc, h3, w3);
    }
    for (; i < e; i++) {
        unsigned p0 = __ldg(&edges[i]);
        int t0 = p0 & 0x3FFFF;
        const __half* s0 = (t0 < N_USERS) ? (usr16 + (size_t)t0 * D)
                                          : (ent16 + (size_t)(t0 - N_USERS) * D);
        uint4 h0 = __ldg((const uint4*)s0 + ln);
        uint4 w0 = __ldg((const uint4*)(ew16 + (size_t)(p0 >> 18) * D) + ln);
        accum_hh(acc, h0, w0);
    }
    float sc = 1.0f / fmaxf(sqrtf(group_sumsq8(acc)), 1e-12f);
    float4 r0 = make_float4(acc[0] * sc, acc[1] * sc, acc[2] * sc, acc[3] * sc);
    float4 r1 = make_float4(acc[4] * sc, acc[5] * sc, acc[6] * sc, acc[7] * sc);
    float4* o = (float4*)(out_node + (size_t)w * D) + ln * 2;
    if (mode == 0) {
        if (w < N_USERS)
            ((uint4*)(usr_next16 + (size_t)w * D))[ln] = pack8(acc, sc);
        __stcs(o, r0);
        __stcs(o + 1, r1);
    } else {
        const float* ip = (w < N_USERS) ? (user0 + (size_t)w * D)
                                        : (ent0 + (size_t)(w - N_USERS) * D);
        const float4* iv = (const float4*)ip + ln * 2;
        float4 i0 = __ldg(iv), i1 = __ldg(iv + 1);
        float4 a0 = __ldcs(o), a1 = __ldcs(o + 1);
        __stcs(o, make_float4(a0.x + i0.x + r0.x, a0.y + i0.y + r0.y,
                              a0.z + i0.z + r0.z, a0.w + i0.w + r0.w));
        __stcs(o + 1, make_float4(a1.x + i1.x + r1.x, a1.y + i1.y + r1.y,
                                  a1.z + i1.z + r1.z, a1.w + i1.w + r1.w));
    }
}

// user: r = l2norm(sum(val * f[col] * ent16[col]))
__global__ void __launch_bounds__(256)
gather_it_h(const __half* __restrict__ ent16, const float* __restrict__ f,
            const int* __restrict__ offs, const int2* __restrict__ edges,
            float* __restrict__ out_user, const float* __restrict__ user0, int mode) {
    int t = blockIdx.x * blockDim.x + threadIdx.x;
    int w = t >> 3, ln = t & 7;
    if (w >= N_USERS) return;
    int s = __ldg(&offs[w]), e = __ldg(&offs[w + 1]);
    float acc[8] = {0, 0, 0, 0, 0, 0, 0, 0};
    int i = s;
    for (; i + 3 < e; i += 4) {
        int2 e0 = __ldg(&edges[i]);
        int2 e1 = __ldg(&edges[i + 1]);
        int2 e2 = __ldg(&edges[i + 2]);
        int2 e3 = __ldg(&edges[i + 3]);
        float v0 = __int_as_float(e0.y) * __ldg(&f[e0.x]);
        float v1 = __int_as_float(e1.y) * __ldg(&f[e1.x]);
        float v2 = __int_as_float(e2.y) * __ldg(&f[e2.x]);
        float v3 = __int_as_float(e3.y) * __ldg(&f[e3.x]);
        uint4 h0 = __ldg((const uint4*)(ent16 + (size_t)e0.x * D) + ln);
        uint4 h1 = __ldg((const uint4*)(ent16 + (size_t)e1.x * D) + ln);
        uint4 h2 = __ldg((const uint4*)(ent16 + (size_t)e2.x * D) + ln);
        uint4 h3 = __ldg((const uint4*)(ent16 + (size_t)e3.x * D) + ln);
        accum_hs(acc, h0, v0); accum_hs(acc, h1, v1);
        accum_hs(acc, h2, v2); accum_hs(acc, h3, v3);
    }
    for (; i < e; i++) {
        int2 e0 = __ldg(&edges[i]);
        float v0 = __int_as_float(e0.y) * __ldg(&f[e0.x]);
        uint4 h0 = __ldg((const uint4*)(ent16 + (size_t)e0.x * D) + ln);
        accum_hs(acc, h0, v0);
    }
    float sc = 1.0f / fmaxf(sqrtf(group_sumsq8(acc)), 1e-12f);
    float4* o = (float4*)(out_user + (size_t)w * D) + ln * 2;
    if (mode == 0) {
        const float4* up = (const float4*)(user0 + (size_t)w * D) + ln * 2;
        float4 u0 = __ldg(up), u1 = __ldg(up + 1);
        __stcs(o, make_float4(u0.x + acc[0] * sc, u0.y + acc[1] * sc,
                              u0.z + acc[2] * sc, u0.w + acc[3] * sc));
        __stcs(o + 1, make_float4(u1.x + acc[4] * sc, u1.y + acc[5] * sc,
                                  u1.z + acc[6] * sc, u1.w + acc[7] * sc));
    } else {
        float4 a0 = __ldcs(o), a1 = __ldcs(o + 1);
        __stcs(o, make_float4(a0.x + acc[0] * sc, a0.y + acc[1] * sc,
                              a0.z + acc[2] * sc, a0.w + acc[3] * sc));
        __stcs(o + 1, make_float4(a1.x + acc[4] * sc, a1.y + acc[5] * sc,
                                  a1.z + acc[6] * sc, a1.w + acc[7] * sc));
    }
}

// ---------------- launch ----------------

static void build_csr(cudaStream_t st, const int* head, int E, int n,
                      int* offs, int* cursor, int* cnt, int* bsums) {
    cudaMemsetAsync(cnt, 0, n * sizeof(int), st);
    count4_k<<<(E / 4 + 255) / 256, 256, 0, st>>>(head, E / 4, cnt);
    int nb = (n + 1023) / 1024;
    scan_block4_k<<<nb, 256, 0, st>>>(cnt, n, offs, bsums);
    scan_final_k<<<1, 256, 0, st>>>(bsums, nb, offs, n, E);
    add_offs4_k<<<(n / 4 + 255) / 256, 256, 0, st>>>(offs, cursor, bsums, n / 4);
}

extern "C" void kernel_launch(void* const* d_in, const int* in_sizes, int n_in,
                              void* d_out, int out_size) {
    const float* user_emb         = (const float*)d_in[0];
    const float* entity_emb       = (const float*)d_in[1];
    const float* weight           = (const float*)d_in[2];
    const float* extra_weight     = (const float*)d_in[3];
    const float* interact_vals    = (const float*)d_in[4];
    const int*   edge_index       = (const int*)d_in[5];
    const int*   edge_type        = (const int*)d_in[6];
    const int*   extra_edge_index = (const int*)d_in[7];
    const int*   extra_edge_type  = (const int*)d_in[8];
    const int*   interact_idx     = (const int*)d_in[9];
    float* out = (float*)d_out;

    const int* kg_head = edge_index;
    const int* kg_tail = edge_index + E_KG;
    const int* pf_head = extra_edge_index;
    const int* pf_tail = extra_edge_index + E_PREF;
    const int* it_rows = interact_idx;
    const int* it_cols = interact_idx + NNZ;

    static cudaStream_t sA = nullptr, sB = nullptr;
    static cudaEvent_t evFork, evCE, evKG0, evIT0, evPref;
    if (!sA) {
        cudaStreamCreateWithFlags(&sA, cudaStreamNonBlocking);
        cudaStreamCreateWithFlags(&sB, cudaStreamNonBlocking);
        cudaEventCreateWithFlags(&evFork, cudaEventDisableTiming);
        cudaEventCreateWithFlags(&evCE,   cudaEventDisableTiming);
        cudaEventCreateWithFlags(&evKG0,  cudaEventDisableTiming);
        cudaEventCreateWithFlags(&evIT0,  cudaEventDisableTiming);
        cudaEventCreateWithFlags(&evPref, cudaEventDisableTiming);
    }

    __half *ent16_in, *usr16_in, *ent_b16, *ent_c16, *usr_b16, *w16, *ew16;
    float *fent_a, *fent_b;
    int *cnt_kg, *cnt_pf, *cnt_it, *bs_kg, *bs_pf, *bs_it;
    int *offs_kg, *offs_pf, *offs_it, *cur_kg, *cur_pf, *cur_it;
    unsigned *ekg, *epf;
    int2 *eit;
    cudaGetSymbolAddress((void**)&ent16_in, g_ent16_in);
    cudaGetSymbolAddress((void**)&usr16_in, g_usr16_in);
    cudaGetSymbolAddress((void**)&ent_b16,  g_ent_b16);
    cudaGetSymbolAddress((void**)&ent_c16,  g_ent_c16);
    cudaGetSymbolAddress((void**)&usr_b16,  g_usr_b16);
    cudaGetSymbolAddress((void**)&w16,      g_w16);
    cudaGetSymbolAddress((void**)&ew16,     g_ew16);
    cudaGetSymbolAddress((void**)&fent_a,   g_fent_a);
    cudaGetSymbolAddress((void**)&fent_b,   g_fent_b);
    cudaGetSymbolAddress((void**)&cnt_kg,   g_cnt_kg);
    cudaGetSymbolAddress((void**)&cnt_pf,   g_cnt_pf);
    cudaGetSymbolAddress((void**)&cnt_it,   g_cnt_it);
    cudaGetSymbolAddress((void**)&bs_kg,    g_bs_kg);
    cudaGetSymbolAddress((void**)&bs_pf,    g_bs_pf);
    cudaGetSymbolAddress((void**)&bs_it,    g_bs_it);
    cudaGetSymbolAddress((void**)&offs_kg,  g_offs_kg);
    cudaGetSymbolAddress((void**)&offs_pf,  g_offs_pf);
    cudaGetSymbolAddress((void**)&offs_it,  g_offs_it);
    cudaGetSymbolAddress((void**)&cur_kg,   g_cur_kg);
    cudaGetSymbolAddress((void**)&cur_pf,   g_cur_pf);
    cudaGetSymbolAddress((void**)&cur_it,   g_cur_it);
    cudaGetSymbolAddress((void**)&ekg,      g_ekg);
    cudaGetSymbolAddress((void**)&epf,      g_epf);
    cudaGetSymbolAddress((void**)&eit,      g_eit);

    float* out_user = out;
    float* out_ent  = out + (size_t)N_USERS * D;
    float* out_node = out + (size_t)N_NODES * D;

    const int GB_ENT  = (N_ENTITIES * 8 + 255) / 256;
    const int GB_NODE = (N_NODES    * 8 + 255) / 256;
    const int GB_USER = (N_USERS    * 8 + 255) / 256;
    const int CV_ENT  = (N_ENTITIES * D / 4 + 255) / 256;
    const int CV_USR  = (N_USERS    * D / 4 + 255) / 256;

    // ---- fork ----
    cudaEventRecord(evFork, 0);
    cudaStreamWaitEvent(sA, evFork, 0);
    cudaStreamWaitEvent(sB, evFork, 0);

    // ---- stream B: fp16 conversions first (off main critical path), then interact CSR
    conv16_k<<<CV_ENT, 256, 0, sB>>>(entity_emb, ent16_in, N_ENTITIES * D / 4);
    conv16_k<<<1, 256, 0, sB>>>(weight, w16, 16 * D / 4);
    cudaEventRecord(evCE, sB);
    build_csr(sB, it_rows, NNZ, N_USERS, offs_it, cur_it, cnt_it, bs_it);
    fill_it4_k<<<(NNZ / 4 + 255) / 256, 256, 0, sB>>>(it_rows, it_cols, interact_vals,
                                                      NNZ / 4, cur_it, eit);

    // ---- stream A: conversions + pref CSR + pref0 ----
    conv16_k<<<CV_USR, 256, 0, sA>>>(user_emb, usr16_in, N_USERS * D / 4);
    conv16_k<<<2, 256, 0, sA>>>(extra_weight, ew16, 32 * D / 4);
    build_csr(sA, pf_head, E_PREF, N_NODES, offs_pf, cur_pf, cnt_pf, bs_pf);
    fill_packed4_k<<<(E_PREF / 4 + 255) / 256, 256, 0, sA>>>(pf_head, pf_tail,
                                                             extra_edge_type, E_PREF / 4,
                                                             0, cur_pf, epf);
    cudaStreamWaitEvent(sA, evCE, 0);
    gather_pref_h<<<GB_NODE, 256, 0, sA>>>(usr16_in, ent16_in, ew16,
                                           offs_pf, epf, usr_b16, out_node,
                                           user_emb, entity_emb, 0);

    // ---- main: kg CSR starts immediately ----
    build_csr(0, kg_head, E_KG, N_ENTITIES, offs_kg, cur_kg, cnt_kg, bs_kg);
    fill_packed4_k<<<(E_KG / 4 + 255) / 256, 256, 0, 0>>>(kg_head, kg_tail, edge_type,
                                                          E_KG / 4, 1, cur_kg, ekg);

    // hop 0: entity agg
    cudaStreamWaitEvent(0, evCE, 0);
    gather_kg_h<<<GB_ENT, 256, 0, 0>>>(ent16_in, w16, offs_kg, ekg,
                                       ent_b16, nullptr, fent_a);
    cudaEventRecord(evKG0, 0);

    // hop 0 interact on stream B (parallel with kg1)
    cudaStreamWaitEvent(sB, evKG0, 0);
    gather_it_h<<<GB_USER, 256, 0, sB>>>(ent_b16, fent_a, offs_it, eit,
                                         out_user, user_emb, 0);
    cudaEventRecord(evIT0, sB);

    // hop 1 pref on stream A
    cudaStreamWaitEvent(sA, evKG0, 0);
    gather_pref_h<<<GB_NODE, 256, 0, sA>>>(usr_b16, ent_b16, ew16,
                                           offs_pf, epf, nullptr, out_node,
                                           user_emb, entity_emb, 1);
    cudaEventRecord(evPref, sA);

    // hop 1: entity agg -> out_ent (fp32, streaming) + ent_c16
    gather_kg_h<<<GB_ENT, 256, 0, 0>>>(ent_b16, w16, offs_kg, ekg,
                                       ent_c16, out_ent, fent_b);

    // hop 1 interact
    cudaStreamWaitEvent(0, evIT0, 0);
    gather_it_h<<<GB_USER, 256, 0, 0>>>(ent_c16, fent_b, offs_it, eit,
                                        out_user, user_emb, 1);

    // ---- join ----
    cudaStreamWaitEvent(0, evPref, 0);
}